// round 14
// baseline (speedup 1.0000x reference)
#include <cuda_runtime.h>
#include <cuda_fp16.h>
#include <cstdint>

namespace {
constexpr int Bc  = 32;
constexpr int Lc  = 4096;
constexpr int Cc  = 512;
constexpr int Hc  = 8;
constexpr int Sc  = 8;
constexpr int NWc = Lc / Sc;
constexpr int Mc  = Bc * Lc;           // 131072
constexpr int NQKV = 3 * Cc;           // 1536
}

// ---------------- scratch (__device__ globals; no allocations) -------------
__device__ __half g_qkv [(size_t)Mc * NQKV];        // fused q|k|v, fp16
__device__ __half g_att [(size_t)Mc * Cc];          // attention out, fp16
__device__ __half g_wt  [(size_t)NQKV * Cc];        // Wq|Wk|Wv transposed [n][k]
__device__ __half g_wpt [(size_t)Cc * Cc];          // Wp transposed
__device__ float  g_bqkv[NQKV];

// ---------------- helpers ---------------------------------------------------
__device__ __forceinline__ uint32_t smem_u32(const void* p) {
    uint32_t a;
    asm("{ .reg .u64 t; cvta.to.shared.u64 t, %1; cvt.u32.u64 %0, t; }" : "=r"(a) : "l"(p));
    return a;
}
#define SW128(off) ((off) ^ (((off) >> 3) & 0x70))
// swizzle for 256B-row fp32 tiles: chunk' = chunk ^ (row & 15)
#define SW256(off) ((off) ^ (((off) >> 4) & 0xF0))

__device__ __forceinline__ void cpa16(uint32_t saddr, const void* g) {
    asm volatile("cp.async.cg.shared.global [%0], [%1], 16;" :: "r"(saddr), "l"(g) : "memory");
}
#define CPA_COMMIT() asm volatile("cp.async.commit_group;" ::: "memory")

__device__ __forceinline__ void ldsm_x4(uint32_t& r0, uint32_t& r1, uint32_t& r2, uint32_t& r3,
                                        uint32_t addr) {
    asm volatile("ldmatrix.sync.aligned.m8n8.x4.shared.b16 {%0,%1,%2,%3}, [%4];"
                 : "=r"(r0), "=r"(r1), "=r"(r2), "=r"(r3) : "r"(addr));
}
__device__ __forceinline__ void mma_fp16(float c[4], const uint32_t a[4], const uint32_t b[2]) {
    asm volatile(
        "mma.sync.aligned.m16n8k16.row.col.f32.f16.f16.f32 "
        "{%0,%1,%2,%3},{%4,%5,%6,%7},{%8,%9},{%0,%1,%2,%3};\n"
        : "+f"(c[0]), "+f"(c[1]), "+f"(c[2]), "+f"(c[3])
        : "r"(a[0]), "r"(a[1]), "r"(a[2]), "r"(a[3]), "r"(b[0]), "r"(b[1]));
}
__device__ __forceinline__ void lds_f4(float4& v, uint32_t a) {
    asm volatile("ld.shared.v4.f32 {%0,%1,%2,%3}, [%4];"
                 : "=f"(v.x), "=f"(v.y), "=f"(v.z), "=f"(v.w) : "r"(a));
}
__device__ __forceinline__ void sts_v4(uint32_t a, uint32_t r0, uint32_t r1,
                                       uint32_t r2, uint32_t r3) {
    asm volatile("st.shared.v4.b32 [%0], {%1,%2,%3,%4};"
                 :: "r"(a), "r"(r0), "r"(r1), "r"(r2), "r"(r3) : "memory");
}

// ---------------- prep kernels ----------------------------------------------
struct WPrepArgs {
    const float* src[4];
    __half* dst[4];
};

__global__ __launch_bounds__(256) void prep_w_all(WPrepArgs args)
{
    __shared__ float t[32][33];
    const float* W  = args.src[blockIdx.z];
    __half* Wt      = args.dst[blockIdx.z];
    const int tx = threadIdx.x & 31, ty = threadIdx.x >> 5;
    const int bn = blockIdx.x * 32, bk = blockIdx.y * 32;
    #pragma unroll
    for (int i = 0; i < 32; i += 8)
        t[ty + i][tx] = W[(size_t)(bk + ty + i) * Cc + bn + tx];
    __syncthreads();
    #pragma unroll
    for (int i = 0; i < 32; i += 8)
        Wt[(size_t)(bn + ty + i) * Cc + bk + tx] = __float2half(t[tx][ty + i]);
}

__global__ void concat_bias(const float* __restrict__ b0, const float* __restrict__ b1,
                            const float* __restrict__ b2, float* __restrict__ dst)
{
    const int i = blockIdx.x * 256 + threadIdx.x;
    if (i < NQKV) {
        const float* s = (i < Cc) ? b0 : (i < 2 * Cc) ? b1 : b2;
        dst[i] = s[i & (Cc - 1)];
    }
}

// ---------------- QKV GEMM: fp32 input, fused convert, fp16 HMMA -----------
// qkv[M,1536](fp16) = fp16(x_rolled[M,512] fp32) @ Wt[1536,512]^T + bias.
// CTA 128x128x64, 8 warps (4M x 2N), warp tile 32x64 (the saturated config).
// A streamed as fp32 via cp.async into SW256 stage; per-K-step conversion
// pass produces the SW128 fp16 A-tile consumed by the unchanged ldmatrix
// mainloop. 2-stage pipeline, 2 CTAs/SM (112 KB smem).
namespace qk {
constexpr int BM = 128, BN = 128, BK = 64;
constexpr int A32_STAGE = BM * BK * 4;          // 32 KB
constexpr int B_STAGE   = BN * BK * 2;          // 16 KB
constexpr int A32_0 = 0;
constexpr int A32_1 = A32_STAGE;
constexpr int B_0   = 2 * A32_STAGE;
constexpr int B_1   = 2 * A32_STAGE + B_STAGE;
constexpr int A16   = 2 * A32_STAGE + 2 * B_STAGE;   // 96 KB
constexpr int DYN_SMEM = A16 + BM * BK * 2;          // 112 KB
constexpr int KSTEPS = Cc / BK;                      // 8
}

__global__ __launch_bounds__(256, 2) void gemm_qkv(
    const float* __restrict__ x, const __half* __restrict__ Wt,
    const float* __restrict__ bias, __half* __restrict__ Out)
{
    using namespace qk;
    extern __shared__ char smem[];
    const uint32_t sbase = smem_u32(smem);

    const int tid  = threadIdx.x;
    const int lane = tid & 31;
    const int warp = tid >> 5;
    const int wm   = warp & 3;       // 4 warps along M (32 rows each)
    const int wn   = warp >> 2;      // 2 warps along N (64 cols each)
    const int grp  = lane >> 2;
    const int tig  = lane & 3;
    const int n0   = blockIdx.x * BN;           // N fastest -> L2-friendly
    const int m0   = blockIdx.y * BM;

    // ---- A loader (fp32, roll folded): row tid>>1, 8 chunks of 16B ----
    const int al_row = tid >> 1;
    const int al_cb  = (tid & 1) * 8;           // chunk base 0 or 8
    const int rg  = m0 + al_row;
    const int pos = rg & (Lc - 1);
    const size_t srow = (size_t)(rg & ~(Lc - 1)) + ((pos + Sc / 2) & (Lc - 1));
    const float* gA = x + srow * Cc + al_cb * 4;      // chunk = 4 floats
    // ---- B loader (fp16): row tid>>1, 4 chunks of 16B ----
    const __half* gB = Wt + (size_t)(n0 + (tid >> 1)) * Cc + (tid & 1) * 32;

    auto load_A = [&](int slot, int ks) {
        const uint32_t sA = sbase + (slot ? A32_1 : A32_0);
        const size_t koff = (size_t)ks * BK;
        #pragma unroll
        for (int i = 0; i < 8; ++i) {
            const uint32_t off = SW256(al_row * 256 + (al_cb + i) * 16);
            cpa16(sA + off, gA + koff + i * 4);
        }
    };
    auto load_B = [&](int slot, int ks) {
        const uint32_t sB = sbase + (slot ? B_1 : B_0);
        const size_t koff = (size_t)ks * BK;
        #pragma unroll
        for (int i = 0; i < 4; ++i) {
            const uint32_t off = SW128((tid >> 1) * 128 + ((tid & 1) * 4 + i) * 16);
            cpa16(sB + off, gB + koff + i * 8);
        }
    };

    // ---- conversion pass: A32(slot) -> A16 (SW128) ----
    const int crow = tid & 127;
    const int cq   = tid >> 7;
    auto convert_A = [&](int slot) {
        const uint32_t sA32 = sbase + (slot ? A32_1 : A32_0);
        const uint32_t sA16 = sbase + A16;
        #pragma unroll
        for (int j = 0; j < 4; ++j) {
            const int c16 = cq * 4 + j;
            float4 fa, fb;
            lds_f4(fa, sA32 + SW256(crow * 256 + (2 * c16) * 16));
            lds_f4(fb, sA32 + SW256(crow * 256 + (2 * c16 + 1) * 16));
            __half2 h0 = __floats2half2_rn(fa.x, fa.y);
            __half2 h1 = __floats2half2_rn(fa.z, fa.w);
            __half2 h2 = __floats2half2_rn(fb.x, fb.y);
            __half2 h3 = __floats2half2_rn(fb.z, fb.w);
            sts_v4(sA16 + SW128(crow * 128 + c16 * 16),
                   *reinterpret_cast<uint32_t*>(&h0), *reinterpret_cast<uint32_t*>(&h1),
                   *reinterpret_cast<uint32_t*>(&h2), *reinterpret_cast<uint32_t*>(&h3));
        }
    };

    // ldmatrix per-lane address components (A from A16, SW128)
    const uint32_t a_row = (uint32_t)(wm * 32 + (lane & 15)) * 128;
    const uint32_t a_kb  = (uint32_t)(lane >> 4) * 16;
    const uint32_t b_row = (uint32_t)(wn * 64 + (lane & 7) + ((lane >> 4) << 3)) * 128;
    const uint32_t b_kb  = (uint32_t)((lane >> 3) & 1) * 16;

    float acc[2][8][4];
    #pragma unroll
    for (int mf = 0; mf < 2; ++mf)
        #pragma unroll
        for (int nf = 0; nf < 8; ++nf)
            #pragma unroll
            for (int t = 0; t < 4; ++t) acc[mf][nf][t] = 0.f;

    load_A(0, 0); load_B(0, 0); CPA_COMMIT();
    load_A(1, 1); load_B(1, 1); CPA_COMMIT();

    for (int ks = 0; ks < KSTEPS; ++ks) {
        const int slot = ks & 1;
        if (ks == KSTEPS - 1) asm volatile("cp.async.wait_group 0;" ::: "memory");
        else                  asm volatile("cp.async.wait_group 1;" ::: "memory");
        __syncthreads();                 // stage ks (A32+B) resident; A16 free

        convert_A(slot);
        __syncthreads();                 // A16 ready; A32(slot) consumed

        if (ks + 2 < KSTEPS) load_A(slot, ks + 2);   // overlaps MMA phase

        const uint32_t sA16 = sbase + A16;
        const uint32_t sB   = sbase + (slot ? B_1 : B_0);
        #pragma unroll
        for (int kk = 0; kk < BK; kk += 16) {
            uint32_t a[2][4], b[4][4];
            #pragma unroll
            for (int mf = 0; mf < 2; ++mf)
                ldsm_x4(a[mf][0], a[mf][1], a[mf][2], a[mf][3],
                        sA16 + SW128(a_row + mf * 16 * 128 + a_kb + kk * 2));
            #pragma unroll
            for (int np = 0; np < 4; ++np)
                ldsm_x4(b[np][0], b[np][1], b[np][2], b[np][3],
                        sB + SW128(b_row + np * 16 * 128 + b_kb + kk * 2));
            #pragma unroll
            for (int mf = 0; mf < 2; ++mf)
                #pragma unroll
                for (int nf = 0; nf < 8; ++nf)
                    mma_fp16(acc[mf][nf], a[mf], &b[nf >> 1][(nf & 1) * 2]);
        }
        __syncthreads();                 // B(slot) consumed CTA-wide
        if (ks + 2 < KSTEPS) { load_B(slot, ks + 2); CPA_COMMIT(); }
    }

    // ---- epilogue: + bias -> fp16 qkv ----
    #pragma unroll
    for (int mf = 0; mf < 2; ++mf) {
        #pragma unroll
        for (int half_ = 0; half_ < 2; ++half_) {
            const int r = m0 + wm * 32 + mf * 16 + grp + half_ * 8;
            __half* op = Out + (size_t)r * NQKV + n0;
            #pragma unroll
            for (int nf = 0; nf < 8; ++nf) {
                const int cN = wn * 64 + nf * 8 + 2 * tig;
                const float v0 = acc[mf][nf][half_ * 2 + 0] + bias[n0 + cN];
                const float v1 = acc[mf][nf][half_ * 2 + 1] + bias[n0 + cN + 1];
                *reinterpret_cast<__half2*>(op + cN) = __floats2half2_rn(v0, v1);
            }
        }
    }
}

// ---------------- fp16 P-GEMM (R3-proven, two-barrier mainloop) ------------
namespace gp {
constexpr int BM = 128, BN = 128, BK = 64;
constexpr int STAGE_A = BM * BK * 2;            // 16 KB
constexpr int STAGE_B = BN * BK * 2;            // 16 KB
constexpr int STAGE   = STAGE_A + STAGE_B;      // 32 KB
constexpr int NSTAGE  = 3;
constexpr int KSTEPS  = Cc / BK;                // 8
constexpr int DYN_SMEM = NSTAGE * STAGE;        // 96 KB
}

__global__ __launch_bounds__(256, 2) void gemm_p(
    const __half* __restrict__ A, const __half* __restrict__ Wt,
    const float* __restrict__ bias, float* __restrict__ Out)
{
    using namespace gp;
    extern __shared__ char smem[];
    const uint32_t sbase = smem_u32(smem);

    const int tid  = threadIdx.x;
    const int lane = tid & 31;
    const int warp = tid >> 5;
    const int wm   = warp & 3;
    const int wn   = warp >> 2;
    const int grp  = lane >> 2;
    const int tig  = lane & 3;
    const int n0   = blockIdx.x * BN;
    const int m0   = blockIdx.y * BM;

    const int ld_row = tid >> 1;
    const int ld_c0  = (tid & 1) * 4;
    const __half* gA = A  + (size_t)(m0 + ld_row) * Cc + ld_c0 * 8;
    const __half* gB = Wt + (size_t)(n0 + ld_row) * Cc + ld_c0 * 8;

    auto load_stage = [&](int slot, int ks) {
        const uint32_t sA = sbase + slot * STAGE;
        const uint32_t sB = sA + STAGE_A;
        const size_t koff = (size_t)ks * BK;
        #pragma unroll
        for (int i = 0; i < 4; ++i) {
            const uint32_t off = SW128(ld_row * 128 + (ld_c0 + i) * 16);
            cpa16(sA + off, gA + koff + i * 8);
            cpa16(sB + off, gB + koff + i * 8);
        }
    };

    const uint32_t a_row = (uint32_t)(wm * 32 + (lane & 15)) * 128;
    const uint32_t a_kb  = (uint32_t)(lane >> 4) * 16;
    const uint32_t b_row = (uint32_t)(wn * 64 + (lane & 7) + ((lane >> 4) << 3)) * 128;
    const uint32_t b_kb  = (uint32_t)((lane >> 3) & 1) * 16;

    float acc[2][8][4];
    #pragma unroll
    for (int mf = 0; mf < 2; ++mf)
        #pragma unroll
        for (int nf = 0; nf < 8; ++nf)
            #pragma unroll
            for (int t = 0; t < 4; ++t) acc[mf][nf][t] = 0.f;

    load_stage(0, 0); CPA_COMMIT();
    load_stage(1, 1); CPA_COMMIT();

    for (int ks = 0; ks < KSTEPS; ++ks) {
        if (ks == KSTEPS - 1) asm volatile("cp.async.wait_group 0;" ::: "memory");
        else                  asm volatile("cp.async.wait_group 1;" ::: "memory");
        __syncthreads();

        const uint32_t sA = sbase + (ks % NSTAGE) * STAGE;
        const uint32_t sB = sA + STAGE_A;

        #pragma unroll
        for (int kk = 0; kk < BK; kk += 16) {
            uint32_t a[2][4], b[4][4];
            #pragma unroll
            for (int mf = 0; mf < 2; ++mf)
                ldsm_x4(a[mf][0], a[mf][1], a[mf][2], a[mf][3],
                        sA + SW128(a_row + mf * 16 * 128 + a_kb + kk * 2));
            #pragma unroll
            for (int np = 0; np < 4; ++np)
                ldsm_x4(b[np][0], b[np][1], b[np][2], b[np][3],
                        sB + SW128(b_row + np * 16 * 128 + b_kb + kk * 2));
            #pragma unroll
            for (int mf = 0; mf < 2; ++mf)
                #pragma unroll
                for (int nf = 0; nf < 8; ++nf)
                    mma_fp16(acc[mf][nf], a[mf], &b[nf >> 1][(nf & 1) * 2]);
        }
        __syncthreads();
        if (ks + 2 < KSTEPS) { load_stage((ks + 2) % NSTAGE, ks + 2); CPA_COMMIT(); }
    }

    // epilogue: + bias, rolled output rows
    #pragma unroll
    for (int mf = 0; mf < 2; ++mf) {
        #pragma unroll
        for (int half_ = 0; half_ < 2; ++half_) {
            const int rg = m0 + wm * 32 + mf * 16 + grp + half_ * 8;
            const int pos = rg & (Lc - 1);
            const size_t drow = (size_t)(rg & ~(Lc - 1)) + ((pos + Sc / 2) & (Lc - 1));
            float* op = Out + drow * Cc + n0;
            #pragma unroll
            for (int nf = 0; nf < 8; ++nf) {
                const int cN = wn * 64 + nf * 8 + 2 * tig;
                float2 o;
                o.x = acc[mf][nf][half_ * 2 + 0] + bias[n0 + cN];
                o.y = acc[mf][nf][half_ * 2 + 1] + bias[n0 + cN + 1];
                *reinterpret_cast<float2*>(op + cN) = o;
            }
        }
    }
}

// ---------------- windowed attention ---------------------------------------
__global__ __launch_bounds__(128) void attn_kernel(
    const __half* __restrict__ qkv, const float* __restrict__ bt,
    __half* __restrict__ att)
{
    __shared__ float sq  [4][Sc * 64];
    __shared__ float sk  [4][Sc * 68];
    __shared__ float sv  [4][Sc * 64];
    __shared__ float satt[4][64];

    const int lane = threadIdx.x & 31;
    const int wid  = threadIdx.x >> 5;
    const int w    = blockIdx.x >> 1;
    const int h    = ((blockIdx.x & 1) << 2) | wid;

    const size_t rowb = (size_t)w * Sc * NQKV + h * 64;

    #pragma unroll
    for (int p = 0; p < 2; ++p) {
        const int c  = p * 32 + lane;
        const int i  = c >> 3;
        const int d8 = (c & 7) * 8;
        const __half* g = qkv + rowb + (size_t)i * NQKV + d8;
        uint4 uq = *reinterpret_cast<const uint4*>(g);
        uint4 uk = *reinterpret_cast<const uint4*>(g + Cc);
        uint4 uv = *reinterpret_cast<const uint4*>(g + 2 * Cc);
        const __half2* hq = reinterpret_cast<const __half2*>(&uq);
        const __half2* hk = reinterpret_cast<const __half2*>(&uk);
        const __half2* hv = reinterpret_cast<const __half2*>(&uv);
        #pragma unroll
        for (int j = 0; j < 4; ++j) {
            const float2 fq = __half22float2(hq[j]);
            const float2 fk = __half22float2(hk[j]);
            const float2 fv = __half22float2(hv[j]);
            sq[wid][i * 64 + d8 + 2 * j]     = fq.x;
            sq[wid][i * 64 + d8 + 2 * j + 1] = fq.y;
            sk[wid][i * 68 + d8 + 2 * j]     = fk.x;
            sk[wid][i * 68 + d8 + 2 * j + 1] = fk.y;
            sv[wid][i * 64 + d8 + 2 * j]     = fv.x;
            sv[wid][i * 64 + d8 + 2 * j + 1] = fv.y;
        }
    }
    __syncwarp();

    const int i0 = lane >> 3;
    const int j  = lane & 7;
    float e0 = 0.f, e1 = 0.f;
    const float* qr0 = &sq[wid][i0 * 64];
    const float* qr1 = &sq[wid][(i0 + 4) * 64];
    const float* kr  = &sk[wid][j * 68];
    #pragma unroll
    for (int d = 0; d < 64; ++d) {
        const float kv = kr[d];
        e0 = fmaf(qr0[d], kv, e0);
        e1 = fmaf(qr1[d], kv, e1);
    }
    const float scale = 0.044194173824159216f;   // 1/sqrt(512)
    e0 = e0 * scale + bt[(j - i0 + 7) * Hc + h];
    e1 = e1 * scale + bt[(j - i0 + 3) * Hc + h];

    if ((w & (NWc - 1)) == NWc - 1) {
        if (j >= 4) e0 -= 100.f;
        else        e1 -= 100.f;
    }

    float m0 = e0, m1 = e1;
    #pragma unroll
    for (int off = 4; off > 0; off >>= 1) {
        m0 = fmaxf(m0, __shfl_xor_sync(0xffffffffu, m0, off));
        m1 = fmaxf(m1, __shfl_xor_sync(0xffffffffu, m1, off));
    }
    float p0 = __expf(e0 - m0), p1 = __expf(e1 - m1);
    float s0 = p0, s1 = p1;
    #pragma unroll
    for (int off = 4; off > 0; off >>= 1) {
        s0 += __shfl_xor_sync(0xffffffffu, s0, off);
        s1 += __shfl_xor_sync(0xffffffffu, s1, off);
    }
    satt[wid][i0 * 8 + j]       = p0 / s0;
    satt[wid][(i0 + 4) * 8 + j] = p1 / s1;
    __syncwarp();

    const size_t ob = (size_t)w * Sc * Cc + h * 64;
    #pragma unroll
    for (int i = 0; i < 8; ++i) {
        float a0 = 0.f, a1 = 0.f;
        #pragma unroll
        for (int t = 0; t < 8; ++t) {
            const float a = satt[wid][i * 8 + t];
            a0 = fmaf(a, sv[wid][t * 64 + lane],      a0);
            a1 = fmaf(a, sv[wid][t * 64 + lane + 32], a1);
        }
        att[ob + (size_t)i * Cc + lane]      = __float2half(a0);
        att[ob + (size_t)i * Cc + lane + 32] = __float2half(a1);
    }
}

// ---------------- launch -----------------------------------------------------
extern "C" void kernel_launch(void* const* d_in, const int* in_sizes, int n_in,
                              void* d_out, int out_size)
{
    const float* x  = (const float*)d_in[0];
    const float* Wq = (const float*)d_in[1];
    const float* bq = (const float*)d_in[2];
    const float* Wk = (const float*)d_in[3];
    const float* bk = (const float*)d_in[4];
    const float* Wv = (const float*)d_in[5];
    const float* bv = (const float*)d_in[6];
    const float* Wp = (const float*)d_in[7];
    const float* bp = (const float*)d_in[8];
    const float* bt = (const float*)d_in[9];
    float* out = (float*)d_out;

    __half *pqkv, *patt, *pwt, *pwpt;
    float* pbqkv;
    cudaGetSymbolAddress((void**)&pqkv, g_qkv);
    cudaGetSymbolAddress((void**)&patt, g_att);
    cudaGetSymbolAddress((void**)&pwt,  g_wt);
    cudaGetSymbolAddress((void**)&pwpt, g_wpt);
    cudaGetSymbolAddress((void**)&pbqkv, g_bqkv);

    cudaFuncSetAttribute(gemm_qkv, cudaFuncAttributeMaxDynamicSharedMemorySize, qk::DYN_SMEM);
    cudaFuncSetAttribute(gemm_p,   cudaFuncAttributeMaxDynamicSharedMemorySize, gp::DYN_SMEM);

    WPrepArgs wa;
    wa.src[0] = Wq; wa.src[1] = Wk; wa.src[2] = Wv; wa.src[3] = Wp;
    wa.dst[0] = pwt;
    wa.dst[1] = pwt + (size_t)Cc * Cc;
    wa.dst[2] = pwt + (size_t)2 * Cc * Cc;
    wa.dst[3] = pwpt;
    prep_w_all<<<dim3(16, 16, 4), 256>>>(wa);
    concat_bias<<<6, 256>>>(bq, bk, bv, pbqkv);

    // QKV GEMM reads fp32 x directly (roll + fp16 conversion fused).
    dim3 g1(NQKV / qk::BN, Mc / qk::BM);   // (12, 1024), N-fastest
    gemm_qkv<<<g1, 256, qk::DYN_SMEM>>>(x, pwt, pbqkv, pqkv);

    attn_kernel<<<Bc * NWc * 2, 128>>>(pqkv, bt, patt);

    dim3 g2(Cc / gp::BN, Mc / gp::BM);     // (4, 1024)
    gemm_p<<<g2, 256, gp::DYN_SMEM>>>(patt, pwpt, bp, out);
}

// round 15
// speedup vs baseline: 1.6031x; 1.6031x over previous
#include <cuda_runtime.h>
#include <cuda_fp16.h>
#include <cstdint>

namespace {
constexpr int Bc  = 32;
constexpr int Lc  = 4096;
constexpr int Cc  = 512;
constexpr int Hc  = 8;
constexpr int Sc  = 8;
constexpr int NWc = Lc / Sc;
constexpr int Mc  = Bc * Lc;           // 131072
constexpr int NQKV = 3 * Cc;           // 1536
}

// ---------------- scratch (__device__ globals; no allocations) -------------
__device__ __half g_x16 [(size_t)Mc * Cc];          // rolled x, fp16
__device__ __half g_qkv [(size_t)Mc * NQKV];        // fused q|k|v, fp16
__device__ __half g_att [(size_t)Mc * Cc];          // attention out, fp16
__device__ __half g_wt  [(size_t)NQKV * Cc];        // Wq|Wk|Wv transposed [n][k]
__device__ __half g_wpt [(size_t)Cc * Cc];          // Wp transposed
__device__ float  g_bqkv[NQKV];

// ---------------- helpers ---------------------------------------------------
__device__ __forceinline__ uint32_t smem_u32(const void* p) {
    uint32_t a;
    asm("{ .reg .u64 t; cvta.to.shared.u64 t, %1; cvt.u32.u64 %0, t; }" : "=r"(a) : "l"(p));
    return a;
}
#define SW128(off) ((off) ^ (((off) >> 3) & 0x70))

__device__ __forceinline__ void cpa16(uint32_t saddr, const void* g) {
    asm volatile("cp.async.cg.shared.global [%0], [%1], 16;" :: "r"(saddr), "l"(g) : "memory");
}
#define CPA_COMMIT() asm volatile("cp.async.commit_group;" ::: "memory")

__device__ __forceinline__ void ldsm_x4(uint32_t& r0, uint32_t& r1, uint32_t& r2, uint32_t& r3,
                                        uint32_t addr) {
    asm volatile("ldmatrix.sync.aligned.m8n8.x4.shared.b16 {%0,%1,%2,%3}, [%4];"
                 : "=r"(r0), "=r"(r1), "=r"(r2), "=r"(r3) : "r"(addr));
}
__device__ __forceinline__ void mma_fp16(float c[4], const uint32_t a[4], const uint32_t b[2]) {
    asm volatile(
        "mma.sync.aligned.m16n8k16.row.col.f32.f16.f16.f32 "
        "{%0,%1,%2,%3},{%4,%5,%6,%7},{%8,%9},{%0,%1,%2,%3};\n"
        : "+f"(c[0]), "+f"(c[1]), "+f"(c[2]), "+f"(c[3])
        : "r"(a[0]), "r"(a[1]), "r"(a[2]), "r"(a[3]), "r"(b[0]), "r"(b[1]));
}

// ---------------- prep kernels ----------------------------------------------
struct WPrepArgs {
    const float* src[4];
    __half* dst[4];
};

__global__ __launch_bounds__(256) void prep_w_all(WPrepArgs args)
{
    __shared__ float t[32][33];
    const float* W  = args.src[blockIdx.z];
    __half* Wt      = args.dst[blockIdx.z];
    const int tx = threadIdx.x & 31, ty = threadIdx.x >> 5;
    const int bn = blockIdx.x * 32, bk = blockIdx.y * 32;
    #pragma unroll
    for (int i = 0; i < 32; i += 8)
        t[ty + i][tx] = W[(size_t)(bk + ty + i) * Cc + bn + tx];
    __syncthreads();
    #pragma unroll
    for (int i = 0; i < 32; i += 8)
        Wt[(size_t)(bn + ty + i) * Cc + bk + tx] = __float2half(t[tx][ty + i]);
}

__global__ void concat_bias(const float* __restrict__ b0, const float* __restrict__ b1,
                            const float* __restrict__ b2, float* __restrict__ dst)
{
    const int i = blockIdx.x * 256 + threadIdx.x;
    if (i < NQKV) {
        const float* s = (i < Cc) ? b0 : (i < 2 * Cc) ? b1 : b2;
        dst[i] = s[i & (Cc - 1)];
    }
}

__global__ __launch_bounds__(256) void convert_x(
    const float* __restrict__ x, __half* __restrict__ xo)
{
    const size_t idx = (size_t)blockIdx.x * 256 + threadIdx.x;  // 8-elt chunk id
    const int row = (int)(idx >> 6);
    const int c8  = (int)(idx & 63) * 8;
    const int pos = row & (Lc - 1);
    const size_t srow = (size_t)(row & ~(Lc - 1)) + ((pos + Sc / 2) & (Lc - 1));
    const float4* src = reinterpret_cast<const float4*>(x + srow * Cc + c8);
    const float4 v0 = src[0], v1 = src[1];
    __half2 o[4];
    o[0] = __floats2half2_rn(v0.x, v0.y);
    o[1] = __floats2half2_rn(v0.z, v0.w);
    o[2] = __floats2half2_rn(v1.x, v1.y);
    o[3] = __floats2half2_rn(v1.z, v1.w);
    *reinterpret_cast<uint4*>(xo + idx * 8) = *reinterpret_cast<uint4*>(o);
}

// ---------------- HMMA GEMM (R3-proven, two-barrier mainloop) --------------
// Out[M, Ntot] = A[M,512](fp16) @ Wt[Ntot,512]^T + bias.
// CTA 128x128x64, 8 warps (4M x 2N), warp tile 32x64, 3-stage cp.async,
// 2 CTAs/SM, f32 accumulate (the pipe-saturated config; 1255us baseline).
namespace gh {
constexpr int BM = 128, BN = 128, BK = 64;
constexpr int STAGE_A = BM * BK * 2;            // 16 KB
constexpr int STAGE_B = BN * BK * 2;            // 16 KB
constexpr int STAGE   = STAGE_A + STAGE_B;      // 32 KB
constexpr int NSTAGE  = 3;
constexpr int KSTEPS  = Cc / BK;                // 8
constexpr int DYN_SMEM = NSTAGE * STAGE;        // 96 KB
}

template <typename OutT, bool ROLL_OUT>
__global__ __launch_bounds__(256, 2) void gemm_hmma(
    const __half* __restrict__ A, const __half* __restrict__ Wt,
    const float* __restrict__ bias, OutT* __restrict__ Out, int ldn)
{
    using namespace gh;
    extern __shared__ char smem[];
    const uint32_t sbase = smem_u32(smem);

    const int tid  = threadIdx.x;
    const int lane = tid & 31;
    const int warp = tid >> 5;
    const int wm   = warp & 3;       // 4 warps along M (32 rows each)
    const int wn   = warp >> 2;      // 2 warps along N (64 cols each)
    const int grp  = lane >> 2;
    const int tig  = lane & 3;
    const int n0   = blockIdx.x * BN;           // N fastest -> L2-friendly
    const int m0   = blockIdx.y * BM;

    const int ld_row = tid >> 1;               // 0..127
    const int ld_c0  = (tid & 1) * 4;          // chunk 0..3 / 4..7
    const __half* gA = A  + (size_t)(m0 + ld_row) * Cc + ld_c0 * 8;
    const __half* gB = Wt + (size_t)(n0 + ld_row) * Cc + ld_c0 * 8;

    auto load_stage = [&](int slot, int ks) {
        const uint32_t sA = sbase + slot * STAGE;
        const uint32_t sB = sA + STAGE_A;
        const size_t koff = (size_t)ks * BK;
        #pragma unroll
        for (int i = 0; i < 4; ++i) {
            const uint32_t off = SW128(ld_row * 128 + (ld_c0 + i) * 16);
            cpa16(sA + off, gA + koff + i * 8);
            cpa16(sB + off, gB + koff + i * 8);
        }
    };

    const uint32_t a_row = (uint32_t)(wm * 32 + (lane & 15)) * 128;
    const uint32_t a_kb  = (uint32_t)(lane >> 4) * 16;
    const uint32_t b_row = (uint32_t)(wn * 64 + (lane & 7) + ((lane >> 4) << 3)) * 128;
    const uint32_t b_kb  = (uint32_t)((lane >> 3) & 1) * 16;

    float acc[2][8][4];
    #pragma unroll
    for (int mf = 0; mf < 2; ++mf)
        #pragma unroll
        for (int nf = 0; nf < 8; ++nf)
            #pragma unroll
            for (int t = 0; t < 4; ++t) acc[mf][nf][t] = 0.f;

    load_stage(0, 0); CPA_COMMIT();
    load_stage(1, 1); CPA_COMMIT();

    for (int ks = 0; ks < KSTEPS; ++ks) {
        if (ks == KSTEPS - 1) asm volatile("cp.async.wait_group 0;" ::: "memory");
        else                  asm volatile("cp.async.wait_group 1;" ::: "memory");
        __syncthreads();

        const uint32_t sA = sbase + (ks % NSTAGE) * STAGE;
        const uint32_t sB = sA + STAGE_A;

        #pragma unroll
        for (int kk = 0; kk < BK; kk += 16) {
            uint32_t a[2][4], b[4][4];
            #pragma unroll
            for (int mf = 0; mf < 2; ++mf)
                ldsm_x4(a[mf][0], a[mf][1], a[mf][2], a[mf][3],
                        sA + SW128(a_row + mf * 16 * 128 + a_kb + kk * 2));
            #pragma unroll
            for (int np = 0; np < 4; ++np)
                ldsm_x4(b[np][0], b[np][1], b[np][2], b[np][3],
                        sB + SW128(b_row + np * 16 * 128 + b_kb + kk * 2));
            #pragma unroll
            for (int mf = 0; mf < 2; ++mf)
                #pragma unroll
                for (int nf = 0; nf < 8; ++nf)
                    mma_fp16(acc[mf][nf], a[mf], &b[nf >> 1][(nf & 1) * 2]);
        }
        __syncthreads();
        if (ks + 2 < KSTEPS) { load_stage((ks + 2) % NSTAGE, ks + 2); CPA_COMMIT(); }
    }

    // ---- epilogue: + bias ----
    #pragma unroll
    for (int mf = 0; mf < 2; ++mf) {
        #pragma unroll
        for (int half_ = 0; half_ < 2; ++half_) {
            const int rg = m0 + wm * 32 + mf * 16 + grp + half_ * 8;
            size_t drow;
            if (ROLL_OUT) {
                const int pos = rg & (Lc - 1);
                drow = (size_t)(rg & ~(Lc - 1)) + ((pos + Sc / 2) & (Lc - 1));
            } else {
                drow = (size_t)rg;
            }
            OutT* op = Out + drow * (size_t)ldn + n0;
            #pragma unroll
            for (int nf = 0; nf < 8; ++nf) {
                const int cN = wn * 64 + nf * 8 + 2 * tig;
                const float v0 = acc[mf][nf][half_ * 2 + 0] + bias[n0 + cN];
                const float v1 = acc[mf][nf][half_ * 2 + 1] + bias[n0 + cN + 1];
                if constexpr (sizeof(OutT) == 2) {
                    *reinterpret_cast<__half2*>(op + cN) = __floats2half2_rn(v0, v1);
                } else {
                    float2 o; o.x = v0; o.y = v1;
                    *reinterpret_cast<float2*>(op + cN) = o;
                }
            }
        }
    }
}

// ---------------- windowed attention (half2 smem, conflict-aware) ----------
// One warp per (window, head). q/k/v stored as __half2, row stride 40 half2
// (80B): q broadcast conflict-free (banks i0*8), k 2-way, v conflict-free.
// fp32 accumulation in identical order to the fp32 version (bit-compatible).
__global__ __launch_bounds__(128) void attn_kernel(
    const __half* __restrict__ qkv, const float* __restrict__ bt,
    __half* __restrict__ att)
{
    constexpr int RS = 40;                    // row stride in half2 units
    __shared__ __half2 sq2[4][Sc * RS];
    __shared__ __half2 sk2[4][Sc * RS];
    __shared__ __half2 sv2[4][Sc * RS];
    __shared__ float   satt[4][64];

    const int lane = threadIdx.x & 31;
    const int wid  = threadIdx.x >> 5;
    const int w    = blockIdx.x >> 1;
    const int h    = ((blockIdx.x & 1) << 2) | wid;

    const size_t rowb = (size_t)w * Sc * NQKV + h * 64;

    // load q/k/v [8 x 64] fp16: one 16B vector store per tensor per c
    #pragma unroll
    for (int p = 0; p < 2; ++p) {
        const int c  = p * 32 + lane;         // 0..63
        const int i  = c >> 3;                // row 0..7
        const int ch = c & 7;                 // 16B chunk 0..7
        const __half* g = qkv + rowb + (size_t)i * NQKV + ch * 8;
        const uint4 uq = *reinterpret_cast<const uint4*>(g);
        const uint4 uk = *reinterpret_cast<const uint4*>(g + Cc);
        const uint4 uv = *reinterpret_cast<const uint4*>(g + 2 * Cc);
        *reinterpret_cast<uint4*>(&sq2[wid][i * RS + ch * 4]) = uq;
        *reinterpret_cast<uint4*>(&sk2[wid][i * RS + ch * 4]) = uk;
        *reinterpret_cast<uint4*>(&sv2[wid][i * RS + ch * 4]) = uv;
    }
    __syncwarp();

    const int i0 = lane >> 3;
    const int j  = lane & 7;
    float e0 = 0.f, e1 = 0.f;
    const __half2* q0p = &sq2[wid][i0 * RS];
    const __half2* q1p = &sq2[wid][(i0 + 4) * RS];
    const __half2* kp  = &sk2[wid][j * RS];
    #pragma unroll
    for (int d2 = 0; d2 < 32; ++d2) {
        const float2 kv = __half22float2(kp[d2]);
        const float2 q0 = __half22float2(q0p[d2]);
        const float2 q1 = __half22float2(q1p[d2]);
        e0 = fmaf(q0.x, kv.x, e0);
        e0 = fmaf(q0.y, kv.y, e0);
        e1 = fmaf(q1.x, kv.x, e1);
        e1 = fmaf(q1.y, kv.y, e1);
    }
    const float scale = 0.044194173824159216f;   // 1/sqrt(512)
    e0 = e0 * scale + bt[(j - i0 + 7) * Hc + h];
    e1 = e1 * scale + bt[(j - i0 + 3) * Hc + h];

    if ((w & (NWc - 1)) == NWc - 1) {            // shift mask on last window
        if (j >= 4) e0 -= 100.f;
        else        e1 -= 100.f;
    }

    float m0 = e0, m1 = e1;
    #pragma unroll
    for (int off = 4; off > 0; off >>= 1) {
        m0 = fmaxf(m0, __shfl_xor_sync(0xffffffffu, m0, off));
        m1 = fmaxf(m1, __shfl_xor_sync(0xffffffffu, m1, off));
    }
    float p0 = __expf(e0 - m0), p1 = __expf(e1 - m1);
    float s0 = p0, s1 = p1;
    #pragma unroll
    for (int off = 4; off > 0; off >>= 1) {
        s0 += __shfl_xor_sync(0xffffffffu, s0, off);
        s1 += __shfl_xor_sync(0xffffffffu, s1, off);
    }
    satt[wid][i0 * 8 + j]       = p0 / s0;
    satt[wid][(i0 + 4) * 8 + j] = p1 / s1;
    __syncwarp();

    // out[i][2*lane .. 2*lane+1] = sum_t att[i][t] * v[t][...]
    const size_t ob = (size_t)w * Sc * Cc + h * 64;
    #pragma unroll
    for (int i = 0; i < 8; ++i) {
        float ax = 0.f, ay = 0.f;
        #pragma unroll
        for (int t = 0; t < 8; ++t) {
            const float a  = satt[wid][i * 8 + t];
            const float2 v = __half22float2(sv2[wid][t * RS + lane]);
            ax = fmaf(a, v.x, ax);
            ay = fmaf(a, v.y, ay);
        }
        *reinterpret_cast<__half2*>(att + ob + (size_t)i * Cc + 2 * lane) =
            __floats2half2_rn(ax, ay);
    }
}

// ---------------- launch -----------------------------------------------------
extern "C" void kernel_launch(void* const* d_in, const int* in_sizes, int n_in,
                              void* d_out, int out_size)
{
    const float* x  = (const float*)d_in[0];
    const float* Wq = (const float*)d_in[1];
    const float* bq = (const float*)d_in[2];
    const float* Wk = (const float*)d_in[3];
    const float* bk = (const float*)d_in[4];
    const float* Wv = (const float*)d_in[5];
    const float* bv = (const float*)d_in[6];
    const float* Wp = (const float*)d_in[7];
    const float* bp = (const float*)d_in[8];
    const float* bt = (const float*)d_in[9];
    float* out = (float*)d_out;

    __half *px16, *pqkv, *patt, *pwt, *pwpt;
    float* pbqkv;
    cudaGetSymbolAddress((void**)&px16, g_x16);
    cudaGetSymbolAddress((void**)&pqkv, g_qkv);
    cudaGetSymbolAddress((void**)&patt, g_att);
    cudaGetSymbolAddress((void**)&pwt,  g_wt);
    cudaGetSymbolAddress((void**)&pwpt, g_wpt);
    cudaGetSymbolAddress((void**)&pbqkv, g_bqkv);

    cudaFuncSetAttribute(gemm_hmma<__half, false>,
                         cudaFuncAttributeMaxDynamicSharedMemorySize, gh::DYN_SMEM);
    cudaFuncSetAttribute(gemm_hmma<float, true>,
                         cudaFuncAttributeMaxDynamicSharedMemorySize, gh::DYN_SMEM);

    WPrepArgs wa;
    wa.src[0] = Wq; wa.src[1] = Wk; wa.src[2] = Wv; wa.src[3] = Wp;
    wa.dst[0] = pwt;
    wa.dst[1] = pwt + (size_t)Cc * Cc;
    wa.dst[2] = pwt + (size_t)2 * Cc * Cc;
    wa.dst[3] = pwpt;
    prep_w_all<<<dim3(16, 16, 4), 256>>>(wa);
    concat_bias<<<6, 256>>>(bq, bk, bv, pbqkv);

    convert_x<<<(Mc * Cc / 8) / 256, 256>>>(x, px16);

    dim3 g1(NQKV / gh::BN, Mc / gh::BM);   // (12, 1024), N-fastest
    gemm_hmma<__half, false><<<g1, 256, gh::DYN_SMEM>>>(px16, pwt, pbqkv, pqkv, NQKV);

    attn_kernel<<<Bc * NWc * 2, 128>>>(pqkv, bt, patt);

    dim3 g2(Cc / gh::BN, Mc / gh::BM);     // (4, 1024)
    gemm_hmma<float, true><<<g2, 256, gh::DYN_SMEM>>>(patt, pwpt, bp, out, Cc);
}